// round 16
// baseline (speedup 1.0000x reference)
#include <cuda_runtime.h>
#include <cstdint>

// ---------------------------------------------------------------------------
// fp4 (bitsandbytes) dequant + GEMV:  y[4, M] = x[4, N] @ W[M, N]^T + bias
//   qweight: numel/2 int32, each holding ONE byte (two nibbles, hi first)
//   absmax : per-64-element block scale; code: 16-entry codebook
//
// R16 mapping: lane owns an int2 (2 packed bytes = 4 consecutive n) at int2
// index I = step*32 + lane. q loads are LDG.64 lane-consecutive -> 1 KB of
// q in flight per warp with distance-1 prefetch (2x R15). x staged per
// 1024-n phase into smem in SoA-by-byte-position form x??_sm[j][i] so the
// inner loop reads are conflict-free lane-consecutive LDS.128.
//   * q: __ldcs streaming, register prefetch distance 1
//   * absmax: per-row block table in smem (LDS broadcast)
//   * epilogue: out zeroed by cudaMemsetAsync; 2 commutative atomicAdds per
//     output (bit-deterministic); bias folded into split 0
//   * grid (2,512)=1024 blocks x 128 thr, 7 CTAs/SM -> single wave
// ---------------------------------------------------------------------------

constexpr int MD = 8192, ND = 8192;
constexpr int NSPLIT = 2;
constexpr int NHALF  = ND / NSPLIT;       // 4096 n per block
constexpr int I2HALF = NHALF / 4;         // 1024 int2 per row-half
constexpr int STEPS  = I2HALF / 32;       // 32 steps (32 int2 per warp-step)
constexpr int RW = 4;                     // rows per warp
constexpr int WPB = 4;                    // warps per block (128 threads)
constexpr int RPB = RW * WPB;             // 16 rows per block
constexpr int PH_I2  = 256;               // int2 cols staged per phase (1024 n)
constexpr int PHASES = I2HALF / PH_I2;    // 4
constexpr int SPP    = PH_I2 / 32;        // 8 steps per phase

static __device__ __forceinline__ unsigned long long pk2(float lo, float hi) {
    unsigned long long r;
    asm("mov.b64 %0, {%1, %2};" : "=l"(r) : "f"(lo), "f"(hi));
    return r;
}
static __device__ __forceinline__ void up2(unsigned long long v, float& lo, float& hi) {
    asm("mov.b64 {%0, %1}, %2;" : "=f"(lo), "=f"(hi) : "l"(v));
}
static __device__ __forceinline__ unsigned long long f2fma(unsigned long long a,
                                                           unsigned long long b,
                                                           unsigned long long c) {
    unsigned long long d;
    asm("fma.rn.f32x2 %0, %1, %2, %3;" : "=l"(d) : "l"(a), "l"(b), "l"(c));
    return d;
}
static __device__ __forceinline__ unsigned long long f2mul(unsigned long long a,
                                                           unsigned long long b) {
    unsigned long long d;
    asm("mul.rn.f32x2 %0, %1, %2;" : "=l"(d) : "l"(a), "l"(b));
    return d;
}
static __device__ __forceinline__ unsigned long long f2add(unsigned long long a,
                                                           unsigned long long b) {
    unsigned long long d;
    asm("add.rn.f32x2 %0, %1, %2;" : "=l"(d) : "l"(a), "l"(b));
    return d;
}

__global__ void __launch_bounds__(128, 7)
fp4_main(const float* __restrict__ x, const int* __restrict__ qw,
         const float* __restrict__ am, const float* __restrict__ code,
         const float* __restrict__ bias, float* __restrict__ out)
{
    __shared__ float am_sm[RPB * 64];              // [row][absmax block], 4 KB
    __shared__ ulonglong2 x01_sm[2][PH_I2];        // [byte j][int2 i], 8 KB
    __shared__ ulonglong2 x23_sm[2][PH_I2];        // 8 KB

    const int lane = threadIdx.x & 31;
    const int wid  = threadIdx.x >> 5;
    const int split   = blockIdx.x;            // 0 or 1
    const int rowbase = blockIdx.y * RPB;
    const int row0    = rowbase + wid * RW;
    const int n0      = split * NHALF;

    // Register-resident codebook: lane l holds code[l & 15]; decode via shfl.
    const float creg = code[lane & 15];

    // ---- absmax preload: [row-in-block][block 0..63], coalesced ----
    for (int k = threadIdx.x; k < RPB * 64; k += 128) {
        const int r  = k >> 6;
        const int bl = k & 63;
        am_sm[k] = am[(rowbase + r) * (ND / 64) + split * (NHALF / 64) + bl];
    }

    // Per-row q streams (int2 granularity) for this N-half.
    const int2* q2 = reinterpret_cast<const int2*>(qw) + row0 * (ND / 4)
                     + split * I2HALF;
    const float4* x0q = reinterpret_cast<const float4*>(x + 0 * ND + n0);
    const float4* x1q = reinterpret_cast<const float4*>(x + 1 * ND + n0);
    const float4* x2q = reinterpret_cast<const float4*>(x + 2 * ND + n0);
    const float4* x3q = reinterpret_cast<const float4*>(x + 3 * ND + n0);

    unsigned long long a01[RW] = {0, 0, 0, 0};
    unsigned long long a23[RW] = {0, 0, 0, 0};

    // ---- q prefetch, distance 1 ----
    int2 bq[RW];
#pragma unroll
    for (int r = 0; r < RW; r++) bq[r] = __ldcs(q2 + r * (ND / 4) + lane);

    for (int ph = 0; ph < PHASES; ++ph) {
        // ---- stage x for this phase: SoA by byte position j ----
        // float4 index == int2 index (4 floats per int2-window).
        const int ibase = ph * PH_I2;
#pragma unroll
        for (int half = 0; half < PH_I2 / 128; ++half) {
            const int i2 = half * 128 + threadIdx.x;   // 0..255
            const float4 f0 = x0q[ibase + i2];
            const float4 f1 = x1q[ibase + i2];
            const float4 f2 = x2q[ibase + i2];
            const float4 f3 = x3q[ibase + i2];
            x01_sm[0][i2] = make_ulonglong2(pk2(f0.x, f1.x), pk2(f0.y, f1.y));
            x01_sm[1][i2] = make_ulonglong2(pk2(f0.z, f1.z), pk2(f0.w, f1.w));
            x23_sm[0][i2] = make_ulonglong2(pk2(f2.x, f3.x), pk2(f2.y, f3.y));
            x23_sm[1][i2] = make_ulonglong2(pk2(f2.z, f3.z), pk2(f2.w, f3.w));
        }
        __syncthreads();   // x phase (and, on ph==0, am_sm) ready

#pragma unroll 2
        for (int t = 0; t < SPP; ++t) {
            const int step = ph * SPP + t;
            // Prefetch next step's q int2s (clamped on the very last step).
            const int nI = (step < STEPS - 1 ? step + 1 : step) * 32 + lane;
            int2 bn[RW];
#pragma unroll
            for (int r = 0; r < RW; r++) bn[r] = __ldcs(q2 + r * (ND / 4) + nI);

            const int i2 = t * 32 + lane;              // phase-local int2 idx
            const int I  = ph * PH_I2 + i2;            // global int2 idx
            const ulonglong2 pa01 = x01_sm[0][i2];     // LDS.128 conflict-free
            const ulonglong2 pb01 = x01_sm[1][i2];
            const ulonglong2 pa23 = x23_sm[0][i2];
            const ulonglong2 pb23 = x23_sm[1][i2];
            const int blk = I >> 4;                    // absmax block (64 n)

#pragma unroll
            for (int r = 0; r < RW; r++) {
                const int b0 = bq[r].x;                // byte 0: n = 4I, 4I+1
                const int b1 = bq[r].y;                // byte 1: n = 4I+2, 4I+3
                const float s = am_sm[(wid * RW + r) * 64 + blk];
                const float c00 = __shfl_sync(0xffffffffu, creg, b0 >> 4);
                const float c01 = __shfl_sync(0xffffffffu, creg, b0 & 15);
                const float c10 = __shfl_sync(0xffffffffu, creg, b1 >> 4);
                const float c11 = __shfl_sync(0xffffffffu, creg, b1 & 15);
                const unsigned long long cc00 = pk2(c00, c00);
                const unsigned long long cc01 = pk2(c01, c01);
                const unsigned long long cc10 = pk2(c10, c10);
                const unsigned long long cc11 = pk2(c11, c11);

                // Unscaled dot over the lane's 4-n window, then fold scale.
                unsigned long long t01 = f2mul(cc00, pa01.x);
                unsigned long long t23 = f2mul(cc00, pa23.x);
                t01 = f2fma(cc01, pa01.y, t01);
                t23 = f2fma(cc01, pa23.y, t23);
                t01 = f2fma(cc10, pb01.x, t01);
                t23 = f2fma(cc10, pb23.x, t23);
                t01 = f2fma(cc11, pb01.y, t01);
                t23 = f2fma(cc11, pb23.y, t23);
                const unsigned long long ss = pk2(s, s);
                a01[r] = f2fma(t01, ss, a01[r]);
                a23[r] = f2fma(t23, ss, a23[r]);
            }

#pragma unroll
            for (int r = 0; r < RW; r++) bq[r] = bn[r];
        }
        __syncthreads();   // all warps done with this phase before restage
    }

    // Butterfly reduction over lanes (packed f32x2 adds).
#pragma unroll
    for (int r = 0; r < RW; r++) {
#pragma unroll
        for (int off = 16; off > 0; off >>= 1) {
            a01[r] = f2add(a01[r], __shfl_xor_sync(0xffffffffu, a01[r], off));
            a23[r] = f2add(a23[r], __shfl_xor_sync(0xffffffffu, a23[r], off));
        }
    }

    // Accumulate into out (zeroed by the memset graph node). Exactly two
    // commutative IEEE adds per output -> bit-deterministic. Bias once (split 0).
#pragma unroll
    for (int r = 0; r < RW; r++) {
        if (lane == r) {
            const int row = row0 + r;
            float y0, y1, y2, y3;
            up2(a01[r], y0, y1);
            up2(a23[r], y2, y3);
            if (split == 0) {
                const float bb = bias[row];
                y0 += bb; y1 += bb; y2 += bb; y3 += bb;
            }
            atomicAdd(&out[0 * MD + row], y0);
            atomicAdd(&out[1 * MD + row], y1);
            atomicAdd(&out[2 * MD + row], y2);
            atomicAdd(&out[3 * MD + row], y3);
        }
    }
}

extern "C" void kernel_launch(void* const* d_in, const int* in_sizes, int n_in,
                              void* d_out, int out_size)
{
    const float* x    = (const float*)d_in[0];
    const int*   qw   = (const int*)d_in[1];
    const float* am   = (const float*)d_in[2];
    const float* code = (const float*)d_in[3];
    const float* bias = (const float*)d_in[4];
    float*       out  = (float*)d_out;

    cudaMemsetAsync(out, 0, (size_t)out_size * sizeof(float));
    dim3 grid(NSPLIT, MD / RPB);              // (2, 512) = 1024 blocks
    fp4_main<<<grid, WPB * 32>>>(x, qw, am, code, bias, out);
}